// round 1
// baseline (speedup 1.0000x reference)
#include <cuda_runtime.h>
#include <cstdint>

#define HID 10
#define HP 47
#define HW 2209          // 47*47
#define HH 96
#define WW 96
#define PIX 9216         // 96*96
#define NB 2

// ---------------- scratch (device globals; no allocation) ----------------
__device__ float g_ppool[2 * 256 * HW];            // [n][256][47*47]
__device__ float g_hupool[12 * HID * HW];          // [i*2+n][10][hw]
__device__ __align__(16) float g_KU[12 * HW * 32]; // per key: k[18],pad2,u[10],pad2
__device__ __align__(16) float g_Q[12 * HW * 20];  // q[18],pad2
__device__ float g_ctx[12 * HID * HW];             // post bn+relu ctx at 47x47
__device__ float g_F[12 * HID * PIX];              // F_dep upsampled
__device__ float g_attsm[12 * 4 * PIX];            // softmaxed att maps
__device__ float g_dattu[2 * 5 * PIX];
__device__ float g_dattl[2 * 3 * PIX];

// output layout (floats)
#define OFF_DU 1105920
#define OFF_DL 1198080
__constant__ int d_CI[6] = {2, 4, 3, 2, 3, 2};
__constant__ long long d_ATTOFF[6] = {1253376, 1290240, 1363968, 1419264, 1456128, 1511424};

// incoming edges per node v: (u, att-channel)
__constant__ int d_ESRC[6][3] = {{1,0,0},{0,2,4},{1,3,0},{2,0,0},{1,5,0},{4,0,0}};
__constant__ int d_ECH [6][3] = {{1,0,0},{1,1,1},{2,1,0},{2,0,0},{3,1,0},{2,0,0}};
__constant__ int d_ECNT[6]    = {1,3,2,1,2,1};

__device__ __forceinline__ void coordf(int s, float* c8) {
    int y = s / HP, x = s % HP;
    const float inv = 1.f / 47.f;
    float xmin = x * inv * 2.f - 1.f, xmax = (x + 1) * inv * 2.f - 1.f;
    float ymin = y * inv * 2.f - 1.f, ymax = (y + 1) * inv * 2.f - 1.f;
    c8[0] = xmin; c8[1] = ymin; c8[2] = xmax; c8[3] = ymax;
    c8[4] = 0.5f * (xmin + xmax); c8[5] = 0.5f * (ymin + ymax);
    c8[6] = inv; c8[7] = inv;
}

__device__ __forceinline__ float sigmoidf_(float x) { return 1.f / (1.f + __expf(-x)); }

// ---------------- 3x3/s2 average pool (valid) ----------------
__global__ void pool_k(const float* __restrict__ src, int which) {
    float* dst = which ? g_hupool : g_ppool;
    int total = which ? 120 * HW : 512 * HW;
    int idx = blockIdx.x * blockDim.x + threadIdx.x;
    if (idx >= total) return;
    int s = idx % HW; int c = idx / HW;
    int oy = s / HP, ox = s % HP;
    const float* p = src + ((size_t)c * HH + oy * 2) * WW + ox * 2;
    float a = 0.f;
#pragma unroll
    for (int dy = 0; dy < 3; dy++) a += p[dy * WW] + p[dy * WW + 1] + p[dy * WW + 2];
    dst[idx] = a * (1.f / 9.f);
}

// ---------------- keys: K = Wk @ [p_pool; coord] ----------------
__global__ __launch_bounds__(256) void keys_k(const float* __restrict__ Wk) {
    __shared__ float sw[18 * 264];
    int bi = blockIdx.y; int i = bi >> 1, n = bi & 1;
    const float* wsrc = Wk + (size_t)i * 18 * 264;
    for (int idx = threadIdx.x; idx < 18 * 264; idx += 256) sw[idx] = wsrc[idx];
    __syncthreads();
    int s = blockIdx.x * 256 + threadIdx.x;
    if (s >= HW) return;
    float acc[18];
#pragma unroll
    for (int o = 0; o < 18; o++) acc[o] = 0.f;
    const float* pp = g_ppool + (size_t)n * 256 * HW + s;
    for (int c = 0; c < 256; c++) {
        float f = pp[(size_t)c * HW];
#pragma unroll
        for (int o = 0; o < 18; o++) acc[o] += sw[o * 264 + c] * f;
    }
    float c8[8]; coordf(s, c8);
#pragma unroll
    for (int c = 0; c < 8; c++) {
        float f = c8[c];
#pragma unroll
        for (int o = 0; o < 18; o++) acc[o] += sw[o * 264 + 256 + c] * f;
    }
    float* rec = g_KU + ((size_t)bi * HW + s) * 32;
#pragma unroll
    for (int o = 0; o < 18; o++) rec[o] = acc[o];
    rec[18] = 0.f; rec[19] = 0.f; rec[30] = 0.f; rec[31] = 0.f;
}

// ---------------- queries: Q = Wq @ [hu_pool; coord] ----------------
__global__ __launch_bounds__(256) void q_k(const float* __restrict__ Wq) {
    __shared__ float sw[324];
    int bi = blockIdx.y; int i = bi >> 1;
    const float* wsrc = Wq + (size_t)i * 324;
    for (int idx = threadIdx.x; idx < 324; idx += 256) sw[idx] = wsrc[idx];
    __syncthreads();
    int s = blockIdx.x * 256 + threadIdx.x;
    if (s >= HW) return;
    float in[18];
    const float* hu = g_hupool + (size_t)bi * HID * HW + s;
#pragma unroll
    for (int c = 0; c < 10; c++) in[c] = hu[(size_t)c * HW];
    coordf(s, in + 10);
    float* q = g_Q + ((size_t)bi * HW + s) * 20;
#pragma unroll
    for (int o = 0; o < 18; o++) {
        float a = 0.f;
#pragma unroll
        for (int c = 0; c < 18; c++) a += sw[o * 18 + c] * in[c];
        q[o] = a;
    }
    q[18] = 0.f; q[19] = 0.f;
}

// ---------------- u = Wp @ relu(bn(Wv @ p_pool)) : tiled SGEMM ----------------
__global__ __launch_bounds__(256) void ugemm_k(const float* __restrict__ Wv,
                                               const float* __restrict__ gv,
                                               const float* __restrict__ bv,
                                               const float* __restrict__ Wp) {
    __shared__ float sh_w[2048];               // [128 rows][16 k]
    __shared__ __align__(16) float sh_p[1024]; // [16 k][64 s]
    __shared__ float sh_v[128 * 65];
    int bi = blockIdx.y; int i = bi >> 1, n = bi & 1;
    int s0 = blockIdx.x * 64;
    int tid = threadIdx.x;
    int tm = tid >> 4, tn = tid & 15;
    const float* Wvp = Wv + (size_t)i * 32768;
    const float* P = g_ppool + (size_t)n * 256 * HW;
    float va[8][4];
#pragma unroll
    for (int r = 0; r < 8; r++)
#pragma unroll
        for (int j = 0; j < 4; j++) va[r][j] = 0.f;

    for (int k0 = 0; k0 < 256; k0 += 16) {
        __syncthreads();
#pragma unroll
        for (int l = 0; l < 8; l++) {
            int idx = tid + l * 256;
            int r = idx >> 4, kk = idx & 15;
            sh_w[idx] = Wvp[r * 256 + k0 + kk];
        }
#pragma unroll
        for (int l = 0; l < 4; l++) {
            int idx = tid + l * 256;
            int kk = idx >> 6, ss = idx & 63;
            int s = s0 + ss;
            sh_p[idx] = (s < HW) ? P[(size_t)(k0 + kk) * HW + s] : 0.f;
        }
        __syncthreads();
#pragma unroll
        for (int kk = 0; kk < 16; kk++) {
            float4 b = *(const float4*)&sh_p[kk * 64 + tn * 4];
#pragma unroll
            for (int rr = 0; rr < 8; rr++) {
                float a = sh_w[(tm * 8 + rr) * 16 + kk];
                va[rr][0] += a * b.x; va[rr][1] += a * b.y;
                va[rr][2] += a * b.z; va[rr][3] += a * b.w;
            }
        }
    }
#pragma unroll
    for (int rr = 0; rr < 8; rr++) {
        int r = tm * 8 + rr;
        float g = gv[i * 128 + r], bb = bv[i * 128 + r];
#pragma unroll
        for (int j = 0; j < 4; j++)
            sh_v[r * 65 + tn * 4 + j] = fmaxf(va[rr][j] * g + bb, 0.f);
    }
    __syncthreads();
    const float* Wpp = Wp + (size_t)i * 1280;
    for (int idx = tid; idx < 640; idx += 256) {
        int o = idx >> 6, col = idx & 63;
        int s = s0 + col;
        if (s < HW) {
            float acc = 0.f;
            const float* wrow = Wpp + o * 128;
#pragma unroll 8
            for (int r = 0; r < 128; r++) acc += wrow[r] * sh_v[r * 65 + col];
            g_KU[((size_t)bi * HW + s) * 32 + 20 + o] = acc;
        }
    }
}

// ---------------- flash attention: ctx10 = relu(bn(u @ softmax(qk)^T)) ----------------
__global__ __launch_bounds__(128) void attn_k(const float* __restrict__ gp,
                                              const float* __restrict__ bp) {
    __shared__ __align__(16) float sh[64 * 32];
    int bi = blockIdx.y; int i = bi >> 1;
    int t = blockIdx.x * 128 + threadIdx.x;
    float4 q0 = {0,0,0,0}, q1 = q0, q2 = q0, q3 = q0, q4 = q0;
    if (t < HW) {
        const float4* qp = (const float4*)(g_Q + ((size_t)bi * HW + t) * 20);
        q0 = qp[0]; q1 = qp[1]; q2 = qp[2]; q3 = qp[3]; q4 = qp[4];
    }
    float m = -1e30f, l = 0.f;
    float acc[10];
#pragma unroll
    for (int j = 0; j < 10; j++) acc[j] = 0.f;

    for (int kt = 0; kt < HW; kt += 64) {
        int nk = min(64, HW - kt);
        __syncthreads();
        const float4* src = (const float4*)(g_KU + ((size_t)bi * HW + kt) * 32);
        for (int r = threadIdx.x; r < nk * 8; r += 128) ((float4*)sh)[r] = src[r];
        __syncthreads();
        for (int kk = 0; kk < nk; kk++) {
            const float4* rec = (const float4*)(sh + kk * 32);
            float4 k0 = rec[0], k1 = rec[1], k2 = rec[2], k3 = rec[3], k4 = rec[4];
            float s = q0.x*k0.x + q0.y*k0.y + q0.z*k0.z + q0.w*k0.w
                    + q1.x*k1.x + q1.y*k1.y + q1.z*k1.z + q1.w*k1.w
                    + q2.x*k2.x + q2.y*k2.y + q2.z*k2.z + q2.w*k2.w
                    + q3.x*k3.x + q3.y*k3.y + q3.z*k3.z + q3.w*k3.w
                    + q4.x*k4.x + q4.y*k4.y;
            if (s > m) {
                float corr = __expf(m - s);
                m = s; l *= corr;
#pragma unroll
                for (int j = 0; j < 10; j++) acc[j] *= corr;
            }
            float p = __expf(s - m);
            l += p;
            float4 u0 = rec[5], u1 = rec[6], u2 = rec[7];
            acc[0] += p*u0.x; acc[1] += p*u0.y; acc[2] += p*u0.z; acc[3] += p*u0.w;
            acc[4] += p*u1.x; acc[5] += p*u1.y; acc[6] += p*u1.z; acc[7] += p*u1.w;
            acc[8] += p*u2.x; acc[9] += p*u2.y;
        }
    }
    if (t < HW) {
        float inv = 1.f / l;
#pragma unroll
        for (int o = 0; o < 10; o++) {
            float c = acc[o] * inv;
            c = c * gp[i * 10 + o] + bp[i * 10 + o];
            g_ctx[((size_t)bi * 10 + o) * HW + t] = fmaxf(c, 0.f);
        }
    }
}

// ---------------- bilinear upsample (align_corners) + att maps + softmax ----------------
__global__ __launch_bounds__(256) void upatt_k(const float* __restrict__ Watt,
                                               const float* __restrict__ batt,
                                               float* __restrict__ out) {
    int bi = blockIdx.y; int i = bi >> 1, n = bi & 1;
    int pix = blockIdx.x * 256 + threadIdx.x;
    if (pix >= PIX) return;
    int y = pix / 96, x = pix % 96;
    const float scale = 46.f / 95.f;
    float fy = y * scale; int y0 = (int)fy; float ry = fy - y0; int y1 = min(y0 + 1, 46);
    float fx = x * scale; int x0 = (int)fx; float rx = fx - x0; int x1 = min(x0 + 1, 46);
    const float* base = g_ctx + (size_t)bi * 10 * HW;
    float F[10];
#pragma unroll
    for (int c = 0; c < 10; c++) {
        const float* cc = base + (size_t)c * HW;
        float v00 = cc[y0 * 47 + x0], v01 = cc[y0 * 47 + x1];
        float v10 = cc[y1 * 47 + x0], v11 = cc[y1 * 47 + x1];
        float a0 = v00 * (1.f - ry) + v10 * ry;
        float a1 = v01 * (1.f - ry) + v11 * ry;
        float v = a0 * (1.f - rx) + a1 * rx;
        F[c] = v;
        g_F[((size_t)bi * 10 + c) * PIX + pix] = v;
    }
    int ci = d_CI[i];
    float a[4]; float mx = -1e30f;
    for (int k = 0; k < ci; k++) {
        float s = batt[i * 4 + k];
#pragma unroll
        for (int c = 0; c < 10; c++) s += Watt[(i * 4 + k) * 10 + c] * F[c];
        a[k] = s; mx = fmaxf(mx, s);
        out[d_ATTOFF[i] + ((size_t)n * ci + k) * PIX + pix] = s;
    }
    float sum = 0.f;
    for (int k = 0; k < ci; k++) { float e = __expf(a[k] - mx); a[k] = e; sum += e; }
    float inv = 1.f / sum;
    for (int k = 0; k < ci; k++)
        g_attsm[((size_t)bi * 4 + k) * PIX + pix] = a[k] * inv;
}

// ---------------- decomposition maps + softmax ----------------
__global__ __launch_bounds__(256) void dmap_k(const float* __restrict__ h_nodes,
                                              const float* __restrict__ Wdu, const float* __restrict__ bdu,
                                              const float* __restrict__ Wdl, const float* __restrict__ bdl,
                                              float* __restrict__ out) {
    int idx = blockIdx.x * 256 + threadIdx.x;
    if (idx >= 2 * PIX) return;
    int n = idx / PIX, pix = idx % PIX;
    float hv[10];
    const float* h0 = h_nodes + (size_t)(0 * 2 + n) * 10 * PIX + pix;
#pragma unroll
    for (int c = 0; c < 10; c++) hv[c] = h0[(size_t)c * PIX];
    {
        float a[5]; float mx = -1e30f;
#pragma unroll
        for (int k = 0; k < 5; k++) {
            float s = bdu[k];
#pragma unroll
            for (int c = 0; c < 10; c++) s += Wdu[k * 10 + c] * hv[c];
            a[k] = s; mx = fmaxf(mx, s);
            out[OFF_DU + ((size_t)n * 5 + k) * PIX + pix] = s;
        }
        float sum = 0.f;
#pragma unroll
        for (int k = 0; k < 5; k++) { a[k] = __expf(a[k] - mx); sum += a[k]; }
        float inv = 1.f / sum;
#pragma unroll
        for (int k = 0; k < 5; k++) g_dattu[((size_t)n * 5 + k) * PIX + pix] = a[k] * inv;
    }
    const float* h1 = h_nodes + (size_t)(1 * 2 + n) * 10 * PIX + pix;
#pragma unroll
    for (int c = 0; c < 10; c++) hv[c] = h1[(size_t)c * PIX];
    {
        float a[3]; float mx = -1e30f;
#pragma unroll
        for (int k = 0; k < 3; k++) {
            float s = bdl[k];
#pragma unroll
            for (int c = 0; c < 10; c++) s += Wdl[k * 10 + c] * hv[c];
            a[k] = s; mx = fmaxf(mx, s);
            out[OFF_DL + ((size_t)n * 3 + k) * PIX + pix] = s;
        }
        float sum = 0.f;
#pragma unroll
        for (int k = 0; k < 3; k++) { a[k] = __expf(a[k] - mx); sum += a[k]; }
        float inv = 1.f / sum;
#pragma unroll
        for (int k = 0; k < 3; k++) g_dattl[((size_t)n * 3 + k) * PIX + pix] = a[k] * inv;
    }
}

// ---------------- decomp conv + edge convs + GRU (fused per node) ----------------
__global__ __launch_bounds__(256) void msg_k(const float* __restrict__ h_nodes,
                                             const float* __restrict__ p_nodes,
                                             const float* __restrict__ Wdec, const float* __restrict__ gdec, const float* __restrict__ bdec,
                                             const float* __restrict__ Wdep, const float* __restrict__ gdep, const float* __restrict__ bdep,
                                             const float* __restrict__ Wg, const float* __restrict__ bg,
                                             const float* __restrict__ Wc, const float* __restrict__ bc,
                                             float* __restrict__ out) {
    __shared__ float sp[10][18][18];
    __shared__ float sm[10][18][18];
    __shared__ float swdec[1800];
    __shared__ float swdep[1800];
    int bi = blockIdx.y; int v = bi >> 1, n = bi & 1;
    int tile = blockIdx.x;
    int ty0 = (tile / 6) * 16, tx0 = (tile % 6) * 16;
    int tid = threadIdx.x;
    int ly = tid >> 4, lx = tid & 15;
    int gy = ty0 + ly, gx = tx0 + lx;
    int gpix = gy * 96 + gx;

    for (int idx = tid; idx < 1800; idx += 256) { swdec[idx] = Wdec[idx]; swdep[idx] = Wdep[idx]; }
    const float* pbase = p_nodes + (size_t)bi * 10 * PIX;
    for (int idx = tid; idx < 10 * 324; idx += 256) {
        int c = idx / 324, r = idx % 324;
        int yy = r / 18, xx = r % 18;
        int py = ty0 - 1 + yy, px = tx0 - 1 + xx;
        float val = 0.f;
        if (py >= 0 && py < 96 && px >= 0 && px < 96) val = pbase[(size_t)c * PIX + py * 96 + px];
        sp[c][yy][xx] = val;
    }
    __syncthreads();

    // p_nodes[v] conv partials (shared by decomp + all edges)
    float pcdec[10], pcdep[10];
#pragma unroll
    for (int o = 0; o < 10; o++) { pcdec[o] = 0.f; pcdep[o] = 0.f; }
    for (int c = 0; c < 10; c++) {
#pragma unroll
        for (int ky = 0; ky < 3; ky++)
#pragma unroll
            for (int kx = 0; kx < 3; kx++) {
                float val = sp[c][ly + ky][lx + kx];
                int wi = (10 + c) * 9 + ky * 3 + kx;
#pragma unroll
                for (int o = 0; o < 10; o++) {
                    pcdec[o] += swdec[o * 180 + wi] * val;
                    pcdep[o] += swdep[o * 180 + wi] * val;
                }
            }
    }

    // decomp source: h_nodes[part] * d_att
    int part = (v < 4) ? 0 : 1;
    int attch = (v < 4) ? (v + 1) : (v - 3);
    const float* hbase = h_nodes + (size_t)(part * 2 + n) * 10 * PIX;
    const float* dbase = (part == 0) ? (g_dattu + (size_t)(n * 5 + attch) * PIX)
                                     : (g_dattl + (size_t)(n * 3 + attch) * PIX);
    for (int idx = tid; idx < 10 * 324; idx += 256) {
        int c = idx / 324, r = idx % 324;
        int yy = r / 18, xx = r % 18;
        int py = ty0 - 1 + yy, px = tx0 - 1 + xx;
        float val = 0.f;
        if (py >= 0 && py < 96 && px >= 0 && px < 96) {
            int g = py * 96 + px;
            val = hbase[(size_t)c * PIX + g] * dbase[g];
        }
        sm[c][yy][xx] = val;
    }
    __syncthreads();

    float msg[10];
    {
        float t[10];
#pragma unroll
        for (int o = 0; o < 10; o++) t[o] = pcdec[o];
        for (int c = 0; c < 10; c++) {
#pragma unroll
            for (int ky = 0; ky < 3; ky++)
#pragma unroll
                for (int kx = 0; kx < 3; kx++) {
                    float val = sm[c][ly + ky][lx + kx];
                    int wi = c * 9 + ky * 3 + kx;
#pragma unroll
                    for (int o = 0; o < 10; o++) t[o] += swdec[o * 180 + wi] * val;
                }
        }
#pragma unroll
        for (int o = 0; o < 10; o++) msg[o] = fmaxf(t[o] * gdec[o] + bdec[o], 0.f);
    }

    // incoming edges
    int ec = d_ECNT[v];
    for (int e = 0; e < ec; e++) {
        int u = d_ESRC[v][e], ch = d_ECH[v][e];
        const float* fb = g_F + (size_t)(u * 2 + n) * 10 * PIX;
        const float* ab = g_attsm + ((size_t)(u * 2 + n) * 4 + ch) * PIX;
        __syncthreads();
        for (int idx = tid; idx < 10 * 324; idx += 256) {
            int c = idx / 324, r = idx % 324;
            int yy = r / 18, xx = r % 18;
            int py = ty0 - 1 + yy, px = tx0 - 1 + xx;
            float val = 0.f;
            if (py >= 0 && py < 96 && px >= 0 && px < 96) {
                int g = py * 96 + px;
                val = fb[(size_t)c * PIX + g] * ab[g];
            }
            sm[c][yy][xx] = val;
        }
        __syncthreads();
        float t[10];
#pragma unroll
        for (int o = 0; o < 10; o++) t[o] = pcdep[o];
        for (int c = 0; c < 10; c++) {
#pragma unroll
            for (int ky = 0; ky < 3; ky++)
#pragma unroll
                for (int kx = 0; kx < 3; kx++) {
                    float val = sm[c][ly + ky][lx + kx];
                    int wi = c * 9 + ky * 3 + kx;
#pragma unroll
                    for (int o = 0; o < 10; o++) t[o] += swdep[o * 180 + wi] * val;
                }
        }
#pragma unroll
        for (int o = 0; o < 10; o++) msg[o] += fmaxf(t[o] * gdep[o] + bdep[o], 0.f);
    }

    // GRU
    float h[10];
#pragma unroll
    for (int c = 0; c < 10; c++) h[c] = sp[c][ly + 1][lx + 1];
    const float* wg = Wg + (size_t)v * 400;
    const float* bgv = bg + (size_t)v * 20;
    float r[10], u[10];
#pragma unroll
    for (int g = 0; g < 10; g++) {
        float s = bgv[g];
#pragma unroll
        for (int j = 0; j < 10; j++) s += wg[g * 20 + j] * msg[j];
#pragma unroll
        for (int j = 0; j < 10; j++) s += wg[g * 20 + 10 + j] * h[j];
        r[g] = sigmoidf_(s);
    }
#pragma unroll
    for (int g = 0; g < 10; g++) {
        float s = bgv[10 + g];
#pragma unroll
        for (int j = 0; j < 10; j++) s += wg[(10 + g) * 20 + j] * msg[j];
#pragma unroll
        for (int j = 0; j < 10; j++) s += wg[(10 + g) * 20 + 10 + j] * h[j];
        u[g] = sigmoidf_(s);
    }
    const float* wc = Wc + (size_t)v * 200;
    const float* bcv = bc + (size_t)v * 10;
#pragma unroll
    for (int o = 0; o < 10; o++) {
        float s = bcv[o];
#pragma unroll
        for (int j = 0; j < 10; j++) s += wc[o * 20 + j] * msg[j];
#pragma unroll
        for (int j = 0; j < 10; j++) s += wc[o * 20 + 10 + j] * (r[j] * h[j]);
        float cc = tanhf(s);
        out[((size_t)bi * 10 + o) * PIX + gpix] = (1.f - u[o]) * h[o] + u[o] * cc;
    }
}

// ---------------- launch ----------------
extern "C" void kernel_launch(void* const* d_in, const int* in_sizes, int n_in,
                              void* d_out, int out_size) {
    const float* h_nodes = (const float*)d_in[1];
    const float* p_nodes = (const float*)d_in[2];
    const float* xp   = (const float*)d_in[3];
    const float* Wq   = (const float*)d_in[4];
    const float* Wk   = (const float*)d_in[5];
    const float* Wv   = (const float*)d_in[6];
    const float* gv   = (const float*)d_in[7];
    const float* bv   = (const float*)d_in[8];
    const float* Wp   = (const float*)d_in[9];
    const float* gp   = (const float*)d_in[10];
    const float* bp   = (const float*)d_in[11];
    const float* Watt = (const float*)d_in[12];
    const float* batt = (const float*)d_in[13];
    const float* Wdu  = (const float*)d_in[14];
    const float* bdu  = (const float*)d_in[15];
    const float* Wdl  = (const float*)d_in[16];
    const float* bdl  = (const float*)d_in[17];
    const float* Wdec = (const float*)d_in[18];
    const float* gdec = (const float*)d_in[19];
    const float* bdec = (const float*)d_in[20];
    const float* Wdep = (const float*)d_in[21];
    const float* gdep = (const float*)d_in[22];
    const float* bdep = (const float*)d_in[23];
    const float* Wg   = (const float*)d_in[24];
    const float* bg   = (const float*)d_in[25];
    const float* Wc   = (const float*)d_in[26];
    const float* bc   = (const float*)d_in[27];
    float* out = (float*)d_out;

    pool_k<<<(512 * HW + 255) / 256, 256>>>(xp, 0);
    pool_k<<<(120 * HW + 255) / 256, 256>>>(p_nodes, 1);
    keys_k<<<dim3(9, 12), 256>>>(Wk);
    q_k<<<dim3(9, 12), 256>>>(Wq);
    ugemm_k<<<dim3(35, 12), 256>>>(Wv, gv, bv, Wp);
    attn_k<<<dim3(18, 12), 128>>>(gp, bp);
    upatt_k<<<dim3(36, 12), 256>>>(Watt, batt, out);
    dmap_k<<<(2 * PIX + 255) / 256, 256>>>(h_nodes, Wdu, bdu, Wdl, bdl, out);
    msg_k<<<dim3(36, 12), 256>>>(h_nodes, p_nodes,
                                 Wdec, gdec, bdec, Wdep, gdep, bdep,
                                 Wg, bg, Wc, bc, out);
}

// round 3
// speedup vs baseline: 1.4872x; 1.4872x over previous
#include <cuda_runtime.h>
#include <cstdint>

#define HID 10
#define HP 47
#define HW 2209          // 47*47
#define HH 96
#define WW 96
#define PIX 9216         // 96*96
#define NB 2
#define SPLIT 8
#define KCH 277          // ceil(HW/SPLIT)

// ---------------- scratch (device globals; no allocation) ----------------
__device__ float g_ppool[2 * 256 * HW];            // [n][256][47*47]
__device__ float g_hupool[12 * HID * HW];          // [i*2+n][10][hw]
__device__ __align__(16) float g_KU[12 * HW * 32]; // per key: k[18],pad2,u[10],pad2
__device__ __align__(16) float g_Q[12 * HW * 20];  // q[18],pad2
__device__ float g_part[SPLIT * 12 * 11 * HW];     // split partials: acc[10], l
__device__ float g_ctx[12 * HID * HW];             // post bn+relu ctx at 47x47
__device__ float g_F[12 * HID * PIX];              // F_dep upsampled
__device__ float g_attsm[12 * 4 * PIX];            // softmaxed att maps
__device__ float g_dattu[2 * 5 * PIX];
__device__ float g_dattl[2 * 3 * PIX];

// output layout (floats)
#define OFF_DU 1105920
#define OFF_DL 1198080
__constant__ int d_CI[6] = {2, 4, 3, 2, 3, 2};
__constant__ long long d_ATTOFF[6] = {1253376, 1290240, 1363968, 1419264, 1456128, 1511424};

// incoming edges per node v: (u, att-channel)
__constant__ int d_ESRC[6][3] = {{1,0,0},{0,2,4},{1,3,0},{2,0,0},{1,5,0},{4,0,0}};
__constant__ int d_ECH [6][3] = {{1,0,0},{1,1,1},{2,1,0},{2,0,0},{3,1,0},{2,0,0}};
__constant__ int d_ECNT[6]    = {1,3,2,1,2,1};

__device__ __forceinline__ void coordf(int s, float* c8) {
    int y = s / HP, x = s % HP;
    const float inv = 1.f / 47.f;
    float xmin = x * inv * 2.f - 1.f, xmax = (x + 1) * inv * 2.f - 1.f;
    float ymin = y * inv * 2.f - 1.f, ymax = (y + 1) * inv * 2.f - 1.f;
    c8[0] = xmin; c8[1] = ymin; c8[2] = xmax; c8[3] = ymax;
    c8[4] = 0.5f * (xmin + xmax); c8[5] = 0.5f * (ymin + ymax);
    c8[6] = inv; c8[7] = inv;
}

__device__ __forceinline__ float sigmoidf_(float x) { return 1.f / (1.f + __expf(-x)); }

// ---------------- 3x3/s2 average pool (valid) ----------------
__global__ void pool_k(const float* __restrict__ src, int which) {
    float* dst = which ? g_hupool : g_ppool;
    int total = which ? 120 * HW : 512 * HW;
    int idx = blockIdx.x * blockDim.x + threadIdx.x;
    if (idx >= total) return;
    int s = idx % HW; int c = idx / HW;
    int oy = s / HP, ox = s % HP;
    const float* p = src + ((size_t)c * HH + oy * 2) * WW + ox * 2;
    float a = 0.f;
#pragma unroll
    for (int dy = 0; dy < 3; dy++) a += p[dy * WW] + p[dy * WW + 1] + p[dy * WW + 2];
    dst[idx] = a * (1.f / 9.f);
}

// ---------------- keys: K = Wk @ [p_pool; coord] ----------------
__global__ __launch_bounds__(256) void keys_k(const float* __restrict__ Wk) {
    __shared__ float sw[18 * 264];
    int bi = blockIdx.y; int i = bi >> 1, n = bi & 1;
    const float* wsrc = Wk + (size_t)i * 18 * 264;
    for (int idx = threadIdx.x; idx < 18 * 264; idx += 256) sw[idx] = wsrc[idx];
    __syncthreads();
    int s = blockIdx.x * 256 + threadIdx.x;
    if (s >= HW) return;
    float acc[18];
#pragma unroll
    for (int o = 0; o < 18; o++) acc[o] = 0.f;
    const float* pp = g_ppool + (size_t)n * 256 * HW + s;
    for (int c = 0; c < 256; c++) {
        float f = pp[(size_t)c * HW];
#pragma unroll
        for (int o = 0; o < 18; o++) acc[o] += sw[o * 264 + c] * f;
    }
    float c8[8]; coordf(s, c8);
#pragma unroll
    for (int c = 0; c < 8; c++) {
        float f = c8[c];
#pragma unroll
        for (int o = 0; o < 18; o++) acc[o] += sw[o * 264 + 256 + c] * f;
    }
    float* rec = g_KU + ((size_t)bi * HW + s) * 32;
#pragma unroll
    for (int o = 0; o < 18; o++) rec[o] = acc[o];
    rec[18] = 0.f; rec[19] = 0.f; rec[30] = 0.f; rec[31] = 0.f;
}

// ---------------- queries: Q = Wq @ [hu_pool; coord] ----------------
__global__ __launch_bounds__(256) void q_k(const float* __restrict__ Wq) {
    __shared__ float sw[324];
    int bi = blockIdx.y; int i = bi >> 1;
    const float* wsrc = Wq + (size_t)i * 324;
    for (int idx = threadIdx.x; idx < 324; idx += 256) sw[idx] = wsrc[idx];
    __syncthreads();
    int s = blockIdx.x * 256 + threadIdx.x;
    if (s >= HW) return;
    float in[18];
    const float* hu = g_hupool + (size_t)bi * HID * HW + s;
#pragma unroll
    for (int c = 0; c < 10; c++) in[c] = hu[(size_t)c * HW];
    coordf(s, in + 10);
    float* q = g_Q + ((size_t)bi * HW + s) * 20;
#pragma unroll
    for (int o = 0; o < 18; o++) {
        float a = 0.f;
#pragma unroll
        for (int c = 0; c < 18; c++) a += sw[o * 18 + c] * in[c];
        q[o] = a;
    }
    q[18] = 0.f; q[19] = 0.f;
}

// ---------------- u = Wp @ relu(bn(Wv @ p_pool)) : tiled SGEMM ----------------
__global__ __launch_bounds__(256) void ugemm_k(const float* __restrict__ Wv,
                                               const float* __restrict__ gv,
                                               const float* __restrict__ bv,
                                               const float* __restrict__ Wp) {
    __shared__ float sh_w[2048];               // [128 rows][16 k]
    __shared__ __align__(16) float sh_p[1024]; // [16 k][64 s]
    __shared__ float sh_v[128 * 65];
    int bi = blockIdx.y; int i = bi >> 1, n = bi & 1;
    int s0 = blockIdx.x * 64;
    int tid = threadIdx.x;
    int tm = tid >> 4, tn = tid & 15;
    const float* Wvp = Wv + (size_t)i * 32768;
    const float* P = g_ppool + (size_t)n * 256 * HW;
    float va[8][4];
#pragma unroll
    for (int r = 0; r < 8; r++)
#pragma unroll
        for (int j = 0; j < 4; j++) va[r][j] = 0.f;

    for (int k0 = 0; k0 < 256; k0 += 16) {
        __syncthreads();
#pragma unroll
        for (int l = 0; l < 8; l++) {
            int idx = tid + l * 256;
            int r = idx >> 4, kk = idx & 15;
            sh_w[idx] = Wvp[r * 256 + k0 + kk];
        }
#pragma unroll
        for (int l = 0; l < 4; l++) {
            int idx = tid + l * 256;
            int kk = idx >> 6, ss = idx & 63;
            int s = s0 + ss;
            sh_p[idx] = (s < HW) ? P[(size_t)(k0 + kk) * HW + s] : 0.f;
        }
        __syncthreads();
#pragma unroll
        for (int kk = 0; kk < 16; kk++) {
            float4 b = *(const float4*)&sh_p[kk * 64 + tn * 4];
#pragma unroll
            for (int rr = 0; rr < 8; rr++) {
                float a = sh_w[(tm * 8 + rr) * 16 + kk];
                va[rr][0] += a * b.x; va[rr][1] += a * b.y;
                va[rr][2] += a * b.z; va[rr][3] += a * b.w;
            }
        }
    }
#pragma unroll
    for (int rr = 0; rr < 8; rr++) {
        int r = tm * 8 + rr;
        float g = gv[i * 128 + r], bb = bv[i * 128 + r];
#pragma unroll
        for (int j = 0; j < 4; j++)
            sh_v[r * 65 + tn * 4 + j] = fmaxf(va[rr][j] * g + bb, 0.f);
    }
    __syncthreads();
    const float* Wpp = Wp + (size_t)i * 1280;
    for (int idx = tid; idx < 640; idx += 256) {
        int o = idx >> 6, col = idx & 63;
        int s = s0 + col;
        if (s < HW) {
            float acc = 0.f;
            const float* wrow = Wpp + o * 128;
#pragma unroll 8
            for (int r = 0; r < 128; r++) acc += wrow[r] * sh_v[r * 65 + col];
            g_KU[((size_t)bi * HW + s) * 32 + 20 + o] = acc;
        }
    }
}

// ---------------- attention partials: no-max softmax, split-K, 2 q/thread ----------------
__global__ __launch_bounds__(256) void attn_part_k() {
    __shared__ __align__(16) float sh[64 * 32];
    int bi = blockIdx.y;
    int split = blockIdx.z;
    int tid = threadIdx.x;
    int q0i = blockIdx.x * 512 + tid * 2;
    int q1i = q0i + 1;
    bool act0 = q0i < HW, act1 = q1i < HW;
    int qa0 = act0 ? q0i : 0;
    int qa1 = act1 ? q1i : 0;
    float4 qA0, qA1, qA2, qA3, qA4, qB0, qB1, qB2, qB3, qB4;
    {
        const float4* qp = (const float4*)(g_Q + ((size_t)bi * HW + qa0) * 20);
        qA0 = qp[0]; qA1 = qp[1]; qA2 = qp[2]; qA3 = qp[3]; qA4 = qp[4];
        qp = (const float4*)(g_Q + ((size_t)bi * HW + qa1) * 20);
        qB0 = qp[0]; qB1 = qp[1]; qB2 = qp[2]; qB3 = qp[3]; qB4 = qp[4];
    }
    int k0 = split * KCH;
    int k1 = min(k0 + KCH, HW);
    float l0 = 0.f, l1 = 0.f;
    float a0[10], a1[10];
#pragma unroll
    for (int j = 0; j < 10; j++) { a0[j] = 0.f; a1[j] = 0.f; }

    for (int kt = k0; kt < k1; kt += 64) {
        int nk = min(64, k1 - kt);
        __syncthreads();
        // cooperative tile load: full 64 records (512 float4); records beyond
        // nk are stale/garbage but never consumed (inner loop bounds at nk).
        // g_KU has >= 1 full tile of slack beyond HW within the padded array.
        const float4* src = (const float4*)(g_KU + ((size_t)bi * HW + kt) * 32);
#pragma unroll
        for (int l = 0; l < 2; l++) ((float4*)sh)[tid + l * 256] = src[tid + l * 256];
        __syncthreads();
        for (int kk = 0; kk < nk; kk++) {
            const float4* rec = (const float4*)(sh + kk * 32);
            float4 k0v = rec[0], k1v = rec[1], k2v = rec[2], k3v = rec[3], k4v = rec[4];
            float s0 = qA0.x*k0v.x + qA0.y*k0v.y + qA0.z*k0v.z + qA0.w*k0v.w
                     + qA1.x*k1v.x + qA1.y*k1v.y + qA1.z*k1v.z + qA1.w*k1v.w
                     + qA2.x*k2v.x + qA2.y*k2v.y + qA2.z*k2v.z + qA2.w*k2v.w
                     + qA3.x*k3v.x + qA3.y*k3v.y + qA3.z*k3v.z + qA3.w*k3v.w
                     + qA4.x*k4v.x + qA4.y*k4v.y;
            float s1 = qB0.x*k0v.x + qB0.y*k0v.y + qB0.z*k0v.z + qB0.w*k0v.w
                     + qB1.x*k1v.x + qB1.y*k1v.y + qB1.z*k1v.z + qB1.w*k1v.w
                     + qB2.x*k2v.x + qB2.y*k2v.y + qB2.z*k2v.z + qB2.w*k2v.w
                     + qB3.x*k3v.x + qB3.y*k3v.y + qB3.z*k3v.z + qB3.w*k3v.w
                     + qB4.x*k4v.x + qB4.y*k4v.y;
            float p0 = __expf(s0);
            float p1 = __expf(s1);
            l0 += p0; l1 += p1;
            float4 u0 = rec[5], u1 = rec[6], u2 = rec[7];
            a0[0] += p0*u0.x; a0[1] += p0*u0.y; a0[2] += p0*u0.z; a0[3] += p0*u0.w;
            a0[4] += p0*u1.x; a0[5] += p0*u1.y; a0[6] += p0*u1.z; a0[7] += p0*u1.w;
            a0[8] += p0*u2.x; a0[9] += p0*u2.y;
            a1[0] += p1*u0.x; a1[1] += p1*u0.y; a1[2] += p1*u0.z; a1[3] += p1*u0.w;
            a1[4] += p1*u1.x; a1[5] += p1*u1.y; a1[6] += p1*u1.z; a1[7] += p1*u1.w;
            a1[8] += p1*u2.x; a1[9] += p1*u2.y;
        }
    }
    float* base = g_part + ((size_t)(split * 12 + bi) * 11) * HW;
    if (act0) {
#pragma unroll
        for (int o = 0; o < 10; o++) base[(size_t)o * HW + q0i] = a0[o];
        base[(size_t)10 * HW + q0i] = l0;
    }
    if (act1) {
#pragma unroll
        for (int o = 0; o < 10; o++) base[(size_t)o * HW + q1i] = a1[o];
        base[(size_t)10 * HW + q1i] = l1;
    }
}

// ---------------- combine partials: /l, bn, relu ----------------
__global__ __launch_bounds__(256) void attn_comb_k(const float* __restrict__ gp,
                                                   const float* __restrict__ bp) {
    int bi = blockIdx.y; int i = bi >> 1;
    int t = blockIdx.x * 256 + threadIdx.x;
    if (t >= HW) return;
    float l = 0.f;
    float acc[10];
#pragma unroll
    for (int o = 0; o < 10; o++) acc[o] = 0.f;
#pragma unroll
    for (int s = 0; s < SPLIT; s++) {
        const float* base = g_part + ((size_t)(s * 12 + bi) * 11) * HW + t;
        l += base[(size_t)10 * HW];
#pragma unroll
        for (int o = 0; o < 10; o++) acc[o] += base[(size_t)o * HW];
    }
    float inv = 1.f / l;
#pragma unroll
    for (int o = 0; o < 10; o++) {
        float c = acc[o] * inv * gp[i * 10 + o] + bp[i * 10 + o];
        g_ctx[((size_t)bi * 10 + o) * HW + t] = fmaxf(c, 0.f);
    }
}

// ---------------- bilinear upsample (align_corners) + att maps + softmax ----------------
__global__ __launch_bounds__(256) void upatt_k(const float* __restrict__ Watt,
                                               const float* __restrict__ batt,
                                               float* __restrict__ out) {
    int bi = blockIdx.y; int i = bi >> 1, n = bi & 1;
    int pix = blockIdx.x * 256 + threadIdx.x;
    if (pix >= PIX) return;
    int y = pix / 96, x = pix % 96;
    const float scale = 46.f / 95.f;
    float fy = y * scale; int y0 = (int)fy; float ry = fy - y0; int y1 = min(y0 + 1, 46);
    float fx = x * scale; int x0 = (int)fx; float rx = fx - x0; int x1 = min(x0 + 1, 46);
    const float* base = g_ctx + (size_t)bi * 10 * HW;
    float F[10];
#pragma unroll
    for (int c = 0; c < 10; c++) {
        const float* cc = base + (size_t)c * HW;
        float v00 = cc[y0 * 47 + x0], v01 = cc[y0 * 47 + x1];
        float v10 = cc[y1 * 47 + x0], v11 = cc[y1 * 47 + x1];
        float a0 = v00 * (1.f - ry) + v10 * ry;
        float a1 = v01 * (1.f - ry) + v11 * ry;
        float v = a0 * (1.f - rx) + a1 * rx;
        F[c] = v;
        g_F[((size_t)bi * 10 + c) * PIX + pix] = v;
    }
    int ci = d_CI[i];
    float a[4]; float mx = -1e30f;
    for (int k = 0; k < ci; k++) {
        float s = batt[i * 4 + k];
#pragma unroll
        for (int c = 0; c < 10; c++) s += Watt[(i * 4 + k) * 10 + c] * F[c];
        a[k] = s; mx = fmaxf(mx, s);
        out[d_ATTOFF[i] + ((size_t)n * ci + k) * PIX + pix] = s;
    }
    float sum = 0.f;
    for (int k = 0; k < ci; k++) { float e = __expf(a[k] - mx); a[k] = e; sum += e; }
    float inv = 1.f / sum;
    for (int k = 0; k < ci; k++)
        g_attsm[((size_t)bi * 4 + k) * PIX + pix] = a[k] * inv;
}

// ---------------- decomposition maps + softmax ----------------
__global__ __launch_bounds__(256) void dmap_k(const float* __restrict__ h_nodes,
                                              const float* __restrict__ Wdu, const float* __restrict__ bdu,
                                              const float* __restrict__ Wdl, const float* __restrict__ bdl,
                                              float* __restrict__ out) {
    int idx = blockIdx.x * 256 + threadIdx.x;
    if (idx >= 2 * PIX) return;
    int n = idx / PIX, pix = idx % PIX;
    float hv[10];
    const float* h0 = h_nodes + (size_t)(0 * 2 + n) * 10 * PIX + pix;
#pragma unroll
    for (int c = 0; c < 10; c++) hv[c] = h0[(size_t)c * PIX];
    {
        float a[5]; float mx = -1e30f;
#pragma unroll
        for (int k = 0; k < 5; k++) {
            float s = bdu[k];
#pragma unroll
            for (int c = 0; c < 10; c++) s += Wdu[k * 10 + c] * hv[c];
            a[k] = s; mx = fmaxf(mx, s);
            out[OFF_DU + ((size_t)n * 5 + k) * PIX + pix] = s;
        }
        float sum = 0.f;
#pragma unroll
        for (int k = 0; k < 5; k++) { a[k] = __expf(a[k] - mx); sum += a[k]; }
        float inv = 1.f / sum;
#pragma unroll
        for (int k = 0; k < 5; k++) g_dattu[((size_t)n * 5 + k) * PIX + pix] = a[k] * inv;
    }
    const float* h1 = h_nodes + (size_t)(1 * 2 + n) * 10 * PIX + pix;
#pragma unroll
    for (int c = 0; c < 10; c++) hv[c] = h1[(size_t)c * PIX];
    {
        float a[3]; float mx = -1e30f;
#pragma unroll
        for (int k = 0; k < 3; k++) {
            float s = bdl[k];
#pragma unroll
            for (int c = 0; c < 10; c++) s += Wdl[k * 10 + c] * hv[c];
            a[k] = s; mx = fmaxf(mx, s);
            out[OFF_DL + ((size_t)n * 3 + k) * PIX + pix] = s;
        }
        float sum = 0.f;
#pragma unroll
        for (int k = 0; k < 3; k++) { a[k] = __expf(a[k] - mx); sum += a[k]; }
        float inv = 1.f / sum;
#pragma unroll
        for (int k = 0; k < 3; k++) g_dattl[((size_t)n * 3 + k) * PIX + pix] = a[k] * inv;
    }
}

// ---------------- decomp conv + edge convs + GRU (fused per node) ----------------
__global__ __launch_bounds__(256) void msg_k(const float* __restrict__ h_nodes,
                                             const float* __restrict__ p_nodes,
                                             const float* __restrict__ Wdec, const float* __restrict__ gdec, const float* __restrict__ bdec,
                                             const float* __restrict__ Wdep, const float* __restrict__ gdep, const float* __restrict__ bdep,
                                             const float* __restrict__ Wg, const float* __restrict__ bg,
                                             const float* __restrict__ Wc, const float* __restrict__ bc,
                                             float* __restrict__ out) {
    __shared__ float sp[10][18][18];
    __shared__ float sm[10][18][18];
    __shared__ float swdec[1800];
    __shared__ float swdep[1800];
    int bi = blockIdx.y; int v = bi >> 1, n = bi & 1;
    int tile = blockIdx.x;
    int ty0 = (tile / 6) * 16, tx0 = (tile % 6) * 16;
    int tid = threadIdx.x;
    int ly = tid >> 4, lx = tid & 15;
    int gy = ty0 + ly, gx = tx0 + lx;
    int gpix = gy * 96 + gx;

    for (int idx = tid; idx < 1800; idx += 256) { swdec[idx] = Wdec[idx]; swdep[idx] = Wdep[idx]; }
    const float* pbase = p_nodes + (size_t)bi * 10 * PIX;
    for (int idx = tid; idx < 10 * 324; idx += 256) {
        int c = idx / 324, r = idx % 324;
        int yy = r / 18, xx = r % 18;
        int py = ty0 - 1 + yy, px = tx0 - 1 + xx;
        float val = 0.f;
        if (py >= 0 && py < 96 && px >= 0 && px < 96) val = pbase[(size_t)c * PIX + py * 96 + px];
        sp[c][yy][xx] = val;
    }
    __syncthreads();

    // p_nodes[v] conv partials (shared by decomp + all edges)
    float pcdec[10], pcdep[10];
#pragma unroll
    for (int o = 0; o < 10; o++) { pcdec[o] = 0.f; pcdep[o] = 0.f; }
    for (int c = 0; c < 10; c++) {
#pragma unroll
        for (int ky = 0; ky < 3; ky++)
#pragma unroll
            for (int kx = 0; kx < 3; kx++) {
                float val = sp[c][ly + ky][lx + kx];
                int wi = (10 + c) * 9 + ky * 3 + kx;
#pragma unroll
                for (int o = 0; o < 10; o++) {
                    pcdec[o] += swdec[o * 180 + wi] * val;
                    pcdep[o] += swdep[o * 180 + wi] * val;
                }
            }
    }

    // decomp source: h_nodes[part] * d_att
    int part = (v < 4) ? 0 : 1;
    int attch = (v < 4) ? (v + 1) : (v - 3);
    const float* hbase = h_nodes + (size_t)(part * 2 + n) * 10 * PIX;
    const float* dbase = (part == 0) ? (g_dattu + (size_t)(n * 5 + attch) * PIX)
                                     : (g_dattl + (size_t)(n * 3 + attch) * PIX);
    for (int idx = tid; idx < 10 * 324; idx += 256) {
        int c = idx / 324, r = idx % 324;
        int yy = r / 18, xx = r % 18;
        int py = ty0 - 1 + yy, px = tx0 - 1 + xx;
        float val = 0.f;
        if (py >= 0 && py < 96 && px >= 0 && px < 96) {
            int g = py * 96 + px;
            val = hbase[(size_t)c * PIX + g] * dbase[g];
        }
        sm[c][yy][xx] = val;
    }
    __syncthreads();

    float msg[10];
    {
        float t[10];
#pragma unroll
        for (int o = 0; o < 10; o++) t[o] = pcdec[o];
        for (int c = 0; c < 10; c++) {
#pragma unroll
            for (int ky = 0; ky < 3; ky++)
#pragma unroll
                for (int kx = 0; kx < 3; kx++) {
                    float val = sm[c][ly + ky][lx + kx];
                    int wi = c * 9 + ky * 3 + kx;
#pragma unroll
                    for (int o = 0; o < 10; o++) t[o] += swdec[o * 180 + wi] * val;
                }
        }
#pragma unroll
        for (int o = 0; o < 10; o++) msg[o] = fmaxf(t[o] * gdec[o] + bdec[o], 0.f);
    }

    // incoming edges
    int ec = d_ECNT[v];
    for (int e = 0; e < ec; e++) {
        int u = d_ESRC[v][e], ch = d_ECH[v][e];
        const float* fb = g_F + (size_t)(u * 2 + n) * 10 * PIX;
        const float* ab = g_attsm + ((size_t)(u * 2 + n) * 4 + ch) * PIX;
        __syncthreads();
        for (int idx = tid; idx < 10 * 324; idx += 256) {
            int c = idx / 324, r = idx % 324;
            int yy = r / 18, xx = r % 18;
            int py = ty0 - 1 + yy, px = tx0 - 1 + xx;
            float val = 0.f;
            if (py >= 0 && py < 96 && px >= 0 && px < 96) {
                int g = py * 96 + px;
                val = fb[(size_t)c * PIX + g] * ab[g];
            }
            sm[c][yy][xx] = val;
        }
        __syncthreads();
        float t[10];
#pragma unroll
        for (int o = 0; o < 10; o++) t[o] = pcdep[o];
        for (int c = 0; c < 10; c++) {
#pragma unroll
            for (int ky = 0; ky < 3; ky++)
#pragma unroll
                for (int kx = 0; kx < 3; kx++) {
                    float val = sm[c][ly + ky][lx + kx];
                    int wi = c * 9 + ky * 3 + kx;
#pragma unroll
                    for (int o = 0; o < 10; o++) t[o] += swdep[o * 180 + wi] * val;
                }
        }
#pragma unroll
        for (int o = 0; o < 10; o++) msg[o] += fmaxf(t[o] * gdep[o] + bdep[o], 0.f);
    }

    // GRU
    float h[10];
#pragma unroll
    for (int c = 0; c < 10; c++) h[c] = sp[c][ly + 1][lx + 1];
    const float* wg = Wg + (size_t)v * 400;
    const float* bgv = bg + (size_t)v * 20;
    float r[10], u[10];
#pragma unroll
    for (int g = 0; g < 10; g++) {
        float s = bgv[g];
#pragma unroll
        for (int j = 0; j < 10; j++) s += wg[g * 20 + j] * msg[j];
#pragma unroll
        for (int j = 0; j < 10; j++) s += wg[g * 20 + 10 + j] * h[j];
        r[g] = sigmoidf_(s);
    }
#pragma unroll
    for (int g = 0; g < 10; g++) {
        float s = bgv[10 + g];
#pragma unroll
        for (int j = 0; j < 10; j++) s += wg[(10 + g) * 20 + j] * msg[j];
#pragma unroll
        for (int j = 0; j < 10; j++) s += wg[(10 + g) * 20 + 10 + j] * h[j];
        u[g] = sigmoidf_(s);
    }
    const float* wc = Wc + (size_t)v * 200;
    const float* bcv = bc + (size_t)v * 10;
#pragma unroll
    for (int o = 0; o < 10; o++) {
        float s = bcv[o];
#pragma unroll
        for (int j = 0; j < 10; j++) s += wc[o * 20 + j] * msg[j];
#pragma unroll
        for (int j = 0; j < 10; j++) s += wc[o * 20 + 10 + j] * (r[j] * h[j]);
        float cc = tanhf(s);
        out[((size_t)bi * 10 + o) * PIX + gpix] = (1.f - u[o]) * h[o] + u[o] * cc;
    }
}

// ---------------- launch ----------------
extern "C" void kernel_launch(void* const* d_in, const int* in_sizes, int n_in,
                              void* d_out, int out_size) {
    const float* h_nodes = (const float*)d_in[1];
    const float* p_nodes = (const float*)d_in[2];
    const float* xp   = (const float*)d_in[3];
    const float* Wq   = (const float*)d_in[4];
    const float* Wk   = (const float*)d_in[5];
    const float* Wv   = (const float*)d_in[6];
    const float* gv   = (const float*)d_in[7];
    const float* bv   = (const float*)d_in[8];
    const float* Wp   = (const float*)d_in[9];
    const float* gp   = (const float*)d_in[10];
    const float* bp   = (const float*)d_in[11];
    const float* Watt = (const float*)d_in[12];
    const float* batt = (const float*)d_in[13];
    const float* Wdu  = (const float*)d_in[14];
    const float* bdu  = (const float*)d_in[15];
    const float* Wdl  = (const float*)d_in[16];
    const float* bdl  = (const float*)d_in[17];
    const float* Wdec = (const float*)d_in[18];
    const float* gdec = (const float*)d_in[19];
    const float* bdec = (const float*)d_in[20];
    const float* Wdep = (const float*)d_in[21];
    const float* gdep = (const float*)d_in[22];
    const float* bdep = (const float*)d_in[23];
    const float* Wg   = (const float*)d_in[24];
    const float* bg   = (const float*)d_in[25];
    const float* Wc   = (const float*)d_in[26];
    const float* bc   = (const float*)d_in[27];
    float* out = (float*)d_out;

    pool_k<<<(512 * HW + 255) / 256, 256>>>(xp, 0);
    pool_k<<<(120 * HW + 255) / 256, 256>>>(p_nodes, 1);
    keys_k<<<dim3(9, 12), 256>>>(Wk);
    q_k<<<dim3(9, 12), 256>>>(Wq);
    ugemm_k<<<dim3(35, 12), 256>>>(Wv, gv, bv, Wp);
    attn_part_k<<<dim3(5, 12, SPLIT), 256>>>();
    attn_comb_k<<<dim3(9, 12), 256>>>(gp, bp);
    upatt_k<<<dim3(36, 12), 256>>>(Watt, batt, out);
    dmap_k<<<(2 * PIX + 255) / 256, 256>>>(h_nodes, Wdu, bdu, Wdl, bdl, out);
    msg_k<<<dim3(36, 12), 256>>>(h_nodes, p_nodes,
                                 Wdec, gdec, bdec, Wdep, gdep, bdep,
                                 Wg, bg, Wc, bc, out);
}

// round 4
// speedup vs baseline: 1.6774x; 1.1279x over previous
#include <cuda_runtime.h>
#include <cstdint>

#define HID 10
#define HP 47
#define HW 2209          // 47*47
#define HH 96
#define WW 96
#define PIX 9216         // 96*96
#define KUP 2240         // padded key count (70 tiles of 32)
#define QP  2240         // padded query count
#define NT  70           // key tiles
#define RS  36           // KU record stride in floats

// ---------------- scratch (device globals; no allocation) ----------------
__device__ float g_ppool[2 * 256 * HW];             // [n][256][47*47]
__device__ float g_hupool[12 * HID * HW];           // [i*2+n][10][hw]
__device__ __align__(16) float g_KU[12 * KUP * RS]; // per key: k[18],0,0,u[10],pad6
__device__ __align__(16) float g_Q[12 * QP * 20];   // q[18],pad2
__device__ float g_ctx[12 * HID * HW];              // post bn+relu ctx at 47x47
__device__ float g_F[12 * HID * PIX];               // F_dep upsampled
__device__ float g_attsm[12 * 4 * PIX];             // softmaxed att maps
__device__ float g_dattu[2 * 5 * PIX];
__device__ float g_dattl[2 * 3 * PIX];

// output layout (floats)
#define OFF_DU 1105920
#define OFF_DL 1198080
__constant__ int d_CI[6] = {2, 4, 3, 2, 3, 2};
__constant__ long long d_ATTOFF[6] = {1253376, 1290240, 1363968, 1419264, 1456128, 1511424};

// incoming edges per node v: (u, att-channel)
__constant__ int d_ESRC[6][3] = {{1,0,0},{0,2,4},{1,3,0},{2,0,0},{1,5,0},{4,0,0}};
__constant__ int d_ECH [6][3] = {{1,0,0},{1,1,1},{2,1,0},{2,0,0},{3,1,0},{2,0,0}};
__constant__ int d_ECNT[6]    = {1,3,2,1,2,1};

__device__ __forceinline__ void coordf(int s, float* c8) {
    int y = s / HP, x = s % HP;
    const float inv = 1.f / 47.f;
    float xmin = x * inv * 2.f - 1.f, xmax = (x + 1) * inv * 2.f - 1.f;
    float ymin = y * inv * 2.f - 1.f, ymax = (y + 1) * inv * 2.f - 1.f;
    c8[0] = xmin; c8[1] = ymin; c8[2] = xmax; c8[3] = ymax;
    c8[4] = 0.5f * (xmin + xmax); c8[5] = 0.5f * (ymin + ymax);
    c8[6] = inv; c8[7] = inv;
}

__device__ __forceinline__ float sigmoidf_(float x) { return 1.f / (1.f + __expf(-x)); }

__device__ __forceinline__ uint32_t f2tf(float f) {
    uint32_t u; asm("cvt.rna.tf32.f32 %0, %1;" : "=r"(u) : "f"(f)); return u;
}

__device__ __forceinline__ void mma8(float d[4], const uint32_t a[4], uint32_t b0, uint32_t b1) {
    asm volatile(
        "mma.sync.aligned.m16n8k8.row.col.f32.tf32.tf32.f32 "
        "{%0,%1,%2,%3}, {%4,%5,%6,%7}, {%8,%9}, {%0,%1,%2,%3};"
        : "+f"(d[0]), "+f"(d[1]), "+f"(d[2]), "+f"(d[3])
        : "r"(a[0]), "r"(a[1]), "r"(a[2]), "r"(a[3]), "r"(b0), "r"(b1));
}

__device__ __forceinline__ void cp16(uint32_t dst, const float4* src) {
    asm volatile("cp.async.cg.shared.global [%0], [%1], 16;" :: "r"(dst), "l"(src));
}

// ---------------- 3x3/s2 average pool (valid) ----------------
__global__ void pool_k(const float* __restrict__ src, int which) {
    float* dst = which ? g_hupool : g_ppool;
    int total = which ? 120 * HW : 512 * HW;
    int idx = blockIdx.x * blockDim.x + threadIdx.x;
    if (idx >= total) return;
    int s = idx % HW; int c = idx / HW;
    int oy = s / HP, ox = s % HP;
    const float* p = src + ((size_t)c * HH + oy * 2) * WW + ox * 2;
    float a = 0.f;
#pragma unroll
    for (int dy = 0; dy < 3; dy++) a += p[dy * WW] + p[dy * WW + 1] + p[dy * WW + 2];
    dst[idx] = a * (1.f / 9.f);
}

// ---------------- keys: K = Wk @ [p_pool; coord]; zero pad records ----------------
__global__ __launch_bounds__(256) void keys_k(const float* __restrict__ Wk) {
    __shared__ float sw[18 * 264];
    int bi = blockIdx.y; int i = bi >> 1, n = bi & 1;
    const float* wsrc = Wk + (size_t)i * 18 * 264;
    for (int idx = threadIdx.x; idx < 18 * 264; idx += 256) sw[idx] = wsrc[idx];
    __syncthreads();
    int s = blockIdx.x * 256 + threadIdx.x;
    if (s >= KUP) return;
    float* rec = g_KU + ((size_t)bi * KUP + s) * RS;
    if (s >= HW) {
#pragma unroll
        for (int o = 0; o < 30; o++) rec[o] = 0.f;
        return;
    }
    float acc[18];
#pragma unroll
    for (int o = 0; o < 18; o++) acc[o] = 0.f;
    const float* pp = g_ppool + (size_t)n * 256 * HW + s;
    for (int c = 0; c < 256; c++) {
        float f = pp[(size_t)c * HW];
#pragma unroll
        for (int o = 0; o < 18; o++) acc[o] += sw[o * 264 + c] * f;
    }
    float c8[8]; coordf(s, c8);
#pragma unroll
    for (int c = 0; c < 8; c++) {
        float f = c8[c];
#pragma unroll
        for (int o = 0; o < 18; o++) acc[o] += sw[o * 264 + 256 + c] * f;
    }
#pragma unroll
    for (int o = 0; o < 18; o++) rec[o] = acc[o];
    rec[18] = 0.f; rec[19] = 0.f;
}

// ---------------- queries: Q = Wq @ [hu_pool; coord] ----------------
__global__ __launch_bounds__(256) void q_k(const float* __restrict__ Wq) {
    __shared__ float sw[324];
    int bi = blockIdx.y; int i = bi >> 1;
    const float* wsrc = Wq + (size_t)i * 324;
    for (int idx = threadIdx.x; idx < 324; idx += 256) sw[idx] = wsrc[idx];
    __syncthreads();
    int s = blockIdx.x * 256 + threadIdx.x;
    if (s >= QP) return;
    float* q = g_Q + ((size_t)bi * QP + s) * 20;
    if (s >= HW) {
#pragma unroll
        for (int o = 0; o < 20; o++) q[o] = 0.f;
        return;
    }
    float in[18];
    const float* hu = g_hupool + (size_t)bi * HID * HW + s;
#pragma unroll
    for (int c = 0; c < 10; c++) in[c] = hu[(size_t)c * HW];
    coordf(s, in + 10);
#pragma unroll
    for (int o = 0; o < 18; o++) {
        float a = 0.f;
#pragma unroll
        for (int c = 0; c < 18; c++) a += sw[o * 18 + c] * in[c];
        q[o] = a;
    }
    q[18] = 0.f; q[19] = 0.f;
}

// ---------------- u = Wp @ relu(bn(Wv @ p_pool)) : tiled SGEMM ----------------
__global__ __launch_bounds__(256) void ugemm_k(const float* __restrict__ Wv,
                                               const float* __restrict__ gv,
                                               const float* __restrict__ bv,
                                               const float* __restrict__ Wp) {
    __shared__ float sh_w[2048];               // [128 rows][16 k]
    __shared__ __align__(16) float sh_p[1024]; // [16 k][64 s]
    __shared__ float sh_v[128 * 65];
    int bi = blockIdx.y; int i = bi >> 1, n = bi & 1;
    int s0 = blockIdx.x * 64;
    int tid = threadIdx.x;
    int tm = tid >> 4, tn = tid & 15;
    const float* Wvp = Wv + (size_t)i * 32768;
    const float* P = g_ppool + (size_t)n * 256 * HW;
    float va[8][4];
#pragma unroll
    for (int r = 0; r < 8; r++)
#pragma unroll
        for (int j = 0; j < 4; j++) va[r][j] = 0.f;

    for (int k0 = 0; k0 < 256; k0 += 16) {
        __syncthreads();
#pragma unroll
        for (int l = 0; l < 8; l++) {
            int idx = tid + l * 256;
            int r = idx >> 4, kk = idx & 15;
            sh_w[idx] = Wvp[r * 256 + k0 + kk];
        }
#pragma unroll
        for (int l = 0; l < 4; l++) {
            int idx = tid + l * 256;
            int kk = idx >> 6, ss = idx & 63;
            int s = s0 + ss;
            sh_p[idx] = (s < HW) ? P[(size_t)(k0 + kk) * HW + s] : 0.f;
        }
        __syncthreads();
#pragma unroll
        for (int kk = 0; kk < 16; kk++) {
            float4 b = *(const float4*)&sh_p[kk * 64 + tn * 4];
#pragma unroll
            for (int rr = 0; rr < 8; rr++) {
                float a = sh_w[(tm * 8 + rr) * 16 + kk];
                va[rr][0] += a * b.x; va[rr][1] += a * b.y;
                va[rr][2] += a * b.z; va[rr][3] += a * b.w;
            }
        }
    }
#pragma unroll
    for (int rr = 0; rr < 8; rr++) {
        int r = tm * 8 + rr;
        float g = gv[i * 128 + r], bb = bv[i * 128 + r];
#pragma unroll
        for (int j = 0; j < 4; j++)
            sh_v[r * 65 + tn * 4 + j] = fmaxf(va[rr][j] * g + bb, 0.f);
    }
    __syncthreads();
    const float* Wpp = Wp + (size_t)i * 1280;
    for (int idx = tid; idx < 640; idx += 256) {
        int o = idx >> 6, col = idx & 63;
        int s = s0 + col;
        if (s < HW) {
            float acc = 0.f;
            const float* wrow = Wpp + o * 128;
#pragma unroll 8
            for (int r = 0; r < 128; r++) acc += wrow[r] * sh_v[r * 65 + col];
            g_KU[((size_t)bi * KUP + s) * RS + 20 + o] = acc;
        }
    }
}

// ---------------- attention: tf32 mma QK^T + SIMT exp/apply ----------------
// block = 128 threads (4 warps), each warp 16 queries. grid (35, 12).
__global__ __launch_bounds__(128) void attn2_k(const float* __restrict__ gp,
                                               const float* __restrict__ bp) {
    __shared__ __align__(16) float sh[2][32 * RS];
    int bi = blockIdx.y; int i = bi >> 1;
    int w = threadIdx.x >> 5, lane = threadIdx.x & 31;
    int g = lane >> 2, tig = lane & 3;
    int q0 = blockIdx.x * 64 + w * 16;

    // A fragments (16 queries x 24 d, 3 k-chunks)
    uint32_t A[3][4];
    const float* qbase = g_Q + (size_t)bi * QP * 20;
#pragma unroll
    for (int kc = 0; kc < 3; kc++) {
        int c0 = kc * 8 + tig, c2 = c0 + 4;
        float v0 = qbase[(q0 + g) * 20 + c0];
        float v1 = qbase[(q0 + g + 8) * 20 + c0];
        float v2 = (c2 < 20) ? qbase[(q0 + g) * 20 + c2] : 0.f;
        float v3 = (c2 < 20) ? qbase[(q0 + g + 8) * 20 + c2] : 0.f;
        A[kc][0] = f2tf(v0); A[kc][1] = f2tf(v1); A[kc][2] = f2tf(v2); A[kc][3] = f2tf(v3);
    }

    float acc0[10], acc1[10], l0 = 0.f, l1 = 0.f;
#pragma unroll
    for (int o = 0; o < 10; o++) { acc0[o] = 0.f; acc1[o] = 0.f; }

    const float* kubase = g_KU + (size_t)bi * KUP * RS;
    uint32_t sbase = (uint32_t)__cvta_generic_to_shared(&sh[0][0]);

    // prefetch tile 0
    {
        const float4* src = (const float4*)(kubase);
        for (int idx = threadIdx.x; idx < 288; idx += 128)
            cp16(sbase + idx * 16, src + idx);
        asm volatile("cp.async.commit_group;");
    }

    for (int t = 0; t < NT; t++) {
        if (t + 1 < NT) {
            uint32_t dst = sbase + ((t + 1) & 1) * (32 * RS * 4);
            const float4* src = (const float4*)(kubase + (size_t)(t + 1) * 32 * RS);
            for (int idx = threadIdx.x; idx < 288; idx += 128)
                cp16(dst + idx * 16, src + idx);
            asm volatile("cp.async.commit_group;");
            asm volatile("cp.async.wait_group 1;");
        } else {
            asm volatile("cp.async.wait_group 0;");
        }
        __syncthreads();
        const float* buf = sh[t & 1];

#pragma unroll
        for (int nc = 0; nc < 4; nc++) {
            float d[4] = {0.f, 0.f, 0.f, 0.f};
            const float* krec = buf + (nc * 8 + g) * RS;
#pragma unroll
            for (int kc = 0; kc < 3; kc++) {
                int r0 = kc * 8 + tig;
                uint32_t b0 = f2tf(krec[r0]);
                uint32_t b1 = (kc < 2) ? f2tf(krec[r0 + 4]) : 0u;
                mma8(d, A[kc], b0, b1);
            }
            int kb = t * 32 + nc * 8 + 2 * tig;
            float p00 = (kb     < HW) ? __expf(d[0]) : 0.f;  // row g,   key kb
            float p01 = (kb + 1 < HW) ? __expf(d[1]) : 0.f;  // row g,   key kb+1
            float p10 = (kb     < HW) ? __expf(d[2]) : 0.f;  // row g+8, key kb
            float p11 = (kb + 1 < HW) ? __expf(d[3]) : 0.f;  // row g+8, key kb+1
            l0 += p00 + p01; l1 += p10 + p11;
            const float* up = buf + (nc * 8 + 2 * tig) * RS + 20;
            {
                float4 ua = *(const float4*)up;
                float4 ub = *(const float4*)(up + 4);
                float2 uc = *(const float2*)(up + 8);
                acc0[0] += p00 * ua.x; acc0[1] += p00 * ua.y; acc0[2] += p00 * ua.z; acc0[3] += p00 * ua.w;
                acc0[4] += p00 * ub.x; acc0[5] += p00 * ub.y; acc0[6] += p00 * ub.z; acc0[7] += p00 * ub.w;
                acc0[8] += p00 * uc.x; acc0[9] += p00 * uc.y;
                acc1[0] += p10 * ua.x; acc1[1] += p10 * ua.y; acc1[2] += p10 * ua.z; acc1[3] += p10 * ua.w;
                acc1[4] += p10 * ub.x; acc1[5] += p10 * ub.y; acc1[6] += p10 * ub.z; acc1[7] += p10 * ub.w;
                acc1[8] += p10 * uc.x; acc1[9] += p10 * uc.y;
            }
            {
                const float* up1 = up + RS;
                float4 ua = *(const float4*)up1;
                float4 ub = *(const float4*)(up1 + 4);
                float2 uc = *(const float2*)(up1 + 8);
                acc0[0] += p01 * ua.x; acc0[1] += p01 * ua.y; acc0[2] += p01 * ua.z; acc0[3] += p01 * ua.w;
                acc0[4] += p01 * ub.x; acc0[5] += p01 * ub.y; acc0[6] += p01 * ub.z; acc0[7] += p01 * ub.w;
                acc0[8] += p01 * uc.x; acc0[9] += p01 * uc.y;
                acc1[0] += p11 * ua.x; acc1[1] += p11 * ua.y; acc1[2] += p11 * ua.z; acc1[3] += p11 * ua.w;
                acc1[4] += p11 * ub.x; acc1[5] += p11 * ub.y; acc1[6] += p11 * ub.z; acc1[7] += p11 * ub.w;
                acc1[8] += p11 * uc.x; acc1[9] += p11 * uc.y;
            }
        }
        __syncthreads();
    }

    // reduce across the 4 threads of each row group
#pragma unroll
    for (int o = 0; o < 10; o++) {
        acc0[o] += __shfl_xor_sync(0xFFFFFFFF, acc0[o], 1);
        acc0[o] += __shfl_xor_sync(0xFFFFFFFF, acc0[o], 2);
        acc1[o] += __shfl_xor_sync(0xFFFFFFFF, acc1[o], 1);
        acc1[o] += __shfl_xor_sync(0xFFFFFFFF, acc1[o], 2);
    }
    l0 += __shfl_xor_sync(0xFFFFFFFF, l0, 1);
    l0 += __shfl_xor_sync(0xFFFFFFFF, l0, 2);
    l1 += __shfl_xor_sync(0xFFFFFFFF, l1, 1);
    l1 += __shfl_xor_sync(0xFFFFFFFF, l1, 2);

    if (tig == 0) {
        int q = q0 + g;
        if (q < HW) {
            float inv = 1.f / l0;
#pragma unroll
            for (int o = 0; o < 10; o++) {
                float c = acc0[o] * inv * gp[i * 10 + o] + bp[i * 10 + o];
                g_ctx[((size_t)bi * 10 + o) * HW + q] = fmaxf(c, 0.f);
            }
        }
        q = q0 + g + 8;
        if (q < HW) {
            float inv = 1.f / l1;
#pragma unroll
            for (int o = 0; o < 10; o++) {
                float c = acc1[o] * inv * gp[i * 10 + o] + bp[i * 10 + o];
                g_ctx[((size_t)bi * 10 + o) * HW + q] = fmaxf(c, 0.f);
            }
        }
    }
}

// ---------------- bilinear upsample (align_corners) + att maps + softmax ----------------
__global__ __launch_bounds__(256) void upatt_k(const float* __restrict__ Watt,
                                               const float* __restrict__ batt,
                                               float* __restrict__ out) {
    int bi = blockIdx.y; int i = bi >> 1, n = bi & 1;
    int pix = blockIdx.x * 256 + threadIdx.x;
    if (pix >= PIX) return;
    int y = pix / 96, x = pix % 96;
    const float scale = 46.f / 95.f;
    float fy = y * scale; int y0 = (int)fy; float ry = fy - y0; int y1 = min(y0 + 1, 46);
    float fx = x * scale; int x0 = (int)fx; float rx = fx - x0; int x1 = min(x0 + 1, 46);
    const float* base = g_ctx + (size_t)bi * 10 * HW;
    float F[10];
#pragma unroll
    for (int c = 0; c < 10; c++) {
        const float* cc = base + (size_t)c * HW;
        float v00 = cc[y0 * 47 + x0], v01 = cc[y0 * 47 + x1];
        float v10 = cc[y1 * 47 + x0], v11 = cc[y1 * 47 + x1];
        float a0 = v00 * (1.f - ry) + v10 * ry;
        float a1 = v01 * (1.f - ry) + v11 * ry;
        float v = a0 * (1.f - rx) + a1 * rx;
        F[c] = v;
        g_F[((size_t)bi * 10 + c) * PIX + pix] = v;
    }
    int ci = d_CI[i];
    float a[4]; float mx = -1e30f;
    for (int k = 0; k < ci; k++) {
        float s = batt[i * 4 + k];
#pragma unroll
        for (int c = 0; c < 10; c++) s += Watt[(i * 4 + k) * 10 + c] * F[c];
        a[k] = s; mx = fmaxf(mx, s);
        out[d_ATTOFF[i] + ((size_t)n * ci + k) * PIX + pix] = s;
    }
    float sum = 0.f;
    for (int k = 0; k < ci; k++) { float e = __expf(a[k] - mx); a[k] = e; sum += e; }
    float inv = 1.f / sum;
    for (int k = 0; k < ci; k++)
        g_attsm[((size_t)bi * 4 + k) * PIX + pix] = a[k] * inv;
}

// ---------------- decomposition maps + softmax ----------------
__global__ __launch_bounds__(256) void dmap_k(const float* __restrict__ h_nodes,
                                              const float* __restrict__ Wdu, const float* __restrict__ bdu,
                                              const float* __restrict__ Wdl, const float* __restrict__ bdl,
                                              float* __restrict__ out) {
    int idx = blockIdx.x * 256 + threadIdx.x;
    if (idx >= 2 * PIX) return;
    int n = idx / PIX, pix = idx % PIX;
    float hv[10];
    const float* h0 = h_nodes + (size_t)(0 * 2 + n) * 10 * PIX + pix;
#pragma unroll
    for (int c = 0; c < 10; c++) hv[c] = h0[(size_t)c * PIX];
    {
        float a[5]; float mx = -1e30f;
#pragma unroll
        for (int k = 0; k < 5; k++) {
            float s = bdu[k];
#pragma unroll
            for (int c = 0; c < 10; c++) s += Wdu[k * 10 + c] * hv[c];
            a[k] = s; mx = fmaxf(mx, s);
            out[OFF_DU + ((size_t)n * 5 + k) * PIX + pix] = s;
        }
        float sum = 0.f;
#pragma unroll
        for (int k = 0; k < 5; k++) { a[k] = __expf(a[k] - mx); sum += a[k]; }
        float inv = 1.f / sum;
#pragma unroll
        for (int k = 0; k < 5; k++) g_dattu[((size_t)n * 5 + k) * PIX + pix] = a[k] * inv;
    }
    const float* h1 = h_nodes + (size_t)(1 * 2 + n) * 10 * PIX + pix;
#pragma unroll
    for (int c = 0; c < 10; c++) hv[c] = h1[(size_t)c * PIX];
    {
        float a[3]; float mx = -1e30f;
#pragma unroll
        for (int k = 0; k < 3; k++) {
            float s = bdl[k];
#pragma unroll
            for (int c = 0; c < 10; c++) s += Wdl[k * 10 + c] * hv[c];
            a[k] = s; mx = fmaxf(mx, s);
            out[OFF_DL + ((size_t)n * 3 + k) * PIX + pix] = s;
        }
        float sum = 0.f;
#pragma unroll
        for (int k = 0; k < 3; k++) { a[k] = __expf(a[k] - mx); sum += a[k]; }
        float inv = 1.f / sum;
#pragma unroll
        for (int k = 0; k < 3; k++) g_dattl[((size_t)n * 3 + k) * PIX + pix] = a[k] * inv;
    }
}

// ---------------- decomp conv + edge convs + GRU (fused per node) ----------------
__global__ __launch_bounds__(256) void msg_k(const float* __restrict__ h_nodes,
                                             const float* __restrict__ p_nodes,
                                             const float* __restrict__ Wdec, const float* __restrict__ gdec, const float* __restrict__ bdec,
                                             const float* __restrict__ Wdep, const float* __restrict__ gdep, const float* __restrict__ bdep,
                                             const float* __restrict__ Wg, const float* __restrict__ bg,
                                             const float* __restrict__ Wc, const float* __restrict__ bc,
                                             float* __restrict__ out) {
    __shared__ float sp[10][18][18];
    __shared__ float sm[10][18][18];
    __shared__ float swdec[1800];
    __shared__ float swdep[1800];
    int bi = blockIdx.y; int v = bi >> 1, n = bi & 1;
    int tile = blockIdx.x;
    int ty0 = (tile / 6) * 16, tx0 = (tile % 6) * 16;
    int tid = threadIdx.x;
    int ly = tid >> 4, lx = tid & 15;
    int gy = ty0 + ly, gx = tx0 + lx;
    int gpix = gy * 96 + gx;

    for (int idx = tid; idx < 1800; idx += 256) { swdec[idx] = Wdec[idx]; swdep[idx] = Wdep[idx]; }
    const float* pbase = p_nodes + (size_t)bi * 10 * PIX;
    for (int idx = tid; idx < 10 * 324; idx += 256) {
        int c = idx / 324, r = idx % 324;
        int yy = r / 18, xx = r % 18;
        int py = ty0 - 1 + yy, px = tx0 - 1 + xx;
        float val = 0.f;
        if (py >= 0 && py < 96 && px >= 0 && px < 96) val = pbase[(size_t)c * PIX + py * 96 + px];
        sp[c][yy][xx] = val;
    }
    __syncthreads();

    // p_nodes[v] conv partials (shared by decomp + all edges)
    float pcdec[10], pcdep[10];
#pragma unroll
    for (int o = 0; o < 10; o++) { pcdec[o] = 0.f; pcdep[o] = 0.f; }
    for (int c = 0; c < 10; c++) {
#pragma unroll
        for (int ky = 0; ky < 3; ky++)
#pragma unroll
            for (int kx = 0; kx < 3; kx++) {
                float val = sp[c][ly + ky][lx + kx];
                int wi = (10 + c) * 9 + ky * 3 + kx;
#pragma unroll
                for (int o = 0; o < 10; o++) {
                    pcdec[o] += swdec[o * 180 + wi] * val;
                    pcdep[o] += swdep[o * 180 + wi] * val;
                }
            }
    }

    // decomp source: h_nodes[part] * d_att
    int part = (v < 4) ? 0 : 1;
    int attch = (v < 4) ? (v + 1) : (v - 3);
    const float* hbase = h_nodes + (size_t)(part * 2 + n) * 10 * PIX;
    const float* dbase = (part == 0) ? (g_dattu + (size_t)(n * 5 + attch) * PIX)
                                     : (g_dattl + (size_t)(n * 3 + attch) * PIX);
    for (int idx = tid; idx < 10 * 324; idx += 256) {
        int c = idx / 324, r = idx % 324;
        int yy = r / 18, xx = r % 18;
        int py = ty0 - 1 + yy, px = tx0 - 1 + xx;
        float val = 0.f;
        if (py >= 0 && py < 96 && px >= 0 && px < 96) {
            int g = py * 96 + px;
            val = hbase[(size_t)c * PIX + g] * dbase[g];
        }
        sm[c][yy][xx] = val;
    }
    __syncthreads();

    float msg[10];
    {
        float t[10];
#pragma unroll
        for (int o = 0; o < 10; o++) t[o] = pcdec[o];
        for (int c = 0; c < 10; c++) {
#pragma unroll
            for (int ky = 0; ky < 3; ky++)
#pragma unroll
                for (int kx = 0; kx < 3; kx++) {
                    float val = sm[c][ly + ky][lx + kx];
                    int wi = c * 9 + ky * 3 + kx;
#pragma unroll
                    for (int o = 0; o < 10; o++) t[o] += swdec[o * 180 + wi] * val;
                }
        }
#pragma unroll
        for (int o = 0; o < 10; o++) msg[o] = fmaxf(t[o] * gdec[o] + bdec[o], 0.f);
    }

    // incoming edges
    int ec = d_ECNT[v];
    for (int e = 0; e < ec; e++) {
        int u = d_ESRC[v][e], ch = d_ECH[v][e];
        const float* fb = g_F + (size_t)(u * 2 + n) * 10 * PIX;
        const float* ab = g_attsm + ((size_t)(u * 2 + n) * 4 + ch) * PIX;
        __syncthreads();
        for (int idx = tid; idx < 10 * 324; idx += 256) {
            int c = idx / 324, r = idx % 324;
            int yy = r / 18, xx = r % 18;
            int py = ty0 - 1 + yy, px = tx0 - 1 + xx;
            float val = 0.f;
            if (py >= 0 && py < 96 && px >= 0 && px < 96) {
                int g = py * 96 + px;
                val = fb[(size_t)c * PIX + g] * ab[g];
            }
            sm[c][yy][xx] = val;
        }
        __syncthreads();
        float t[10];
#pragma unroll
        for (int o = 0; o < 10; o++) t[o] = pcdep[o];
        for (int c = 0; c < 10; c++) {
#pragma unroll
            for (int ky = 0; ky < 3; ky++)
#pragma unroll
                for (int kx = 0; kx < 3; kx++) {
                    float val = sm[c][ly + ky][lx + kx];
                    int wi = c * 9 + ky * 3 + kx;
#pragma unroll
                    for (int o = 0; o < 10; o++) t[o] += swdep[o * 180 + wi] * val;
                }
        }
#pragma unroll
        for (int o = 0; o < 10; o++) msg[o] += fmaxf(t[o] * gdep[o] + bdep[o], 0.f);
    }

    // GRU
    float h[10];
#pragma unroll
    for (int c = 0; c < 10; c++) h[c] = sp[c][ly + 1][lx + 1];
    const float* wg = Wg + (size_t)v * 400;
    const float* bgv = bg + (size_t)v * 20;
    float r[10], u[10];
#pragma unroll
    for (int g = 0; g < 10; g++) {
        float s = bgv[g];
#pragma unroll
        for (int j = 0; j < 10; j++) s += wg[g * 20 + j] * msg[j];
#pragma unroll
        for (int j = 0; j < 10; j++) s += wg[g * 20 + 10 + j] * h[j];
        r[g] = sigmoidf_(s);
    }
#pragma unroll
    for (int g = 0; g < 10; g++) {
        float s = bgv[10 + g];
#pragma unroll
        for (int j = 0; j < 10; j++) s += wg[(10 + g) * 20 + j] * msg[j];
#pragma unroll
        for (int j = 0; j < 10; j++) s += wg[(10 + g) * 20 + 10 + j] * h[j];
        u[g] = sigmoidf_(s);
    }
    const float* wc = Wc + (size_t)v * 200;
    const float* bcv = bc + (size_t)v * 10;
#pragma unroll
    for (int o = 0; o < 10; o++) {
        float s = bcv[o];
#pragma unroll
        for (int j = 0; j < 10; j++) s += wc[o * 20 + j] * msg[j];
#pragma unroll
        for (int j = 0; j < 10; j++) s += wc[o * 20 + 10 + j] * (r[j] * h[j]);
        float cc = tanhf(s);
        out[((size_t)bi * 10 + o) * PIX + gpix] = (1.f - u[o]) * h[o] + u[o] * cc;
    }
}

// ---------------- launch ----------------
extern "C" void kernel_launch(void* const* d_in, const int* in_sizes, int n_in,
                              void* d_out, int out_size) {
    const float* h_nodes = (const float*)d_in[1];
    const float* p_nodes = (const float*)d_in[2];
    const float* xp   = (const float*)d_in[3];
    const float* Wq   = (const float*)d_in[4];
    const float* Wk   = (const float*)d_in[5];
    const float* Wv   = (const float*)d_in[6];
    const float* gv   = (const float*)d_in[7];
    const float* bv   = (const float*)d_in[8];
    const float* Wp   = (const float*)d_in[9];
    const float* gp   = (const float*)d_in[10];
    const float* bp   = (const float*)d_in[11];
    const float* Watt = (const float*)d_in[12];
    const float* batt = (const float*)d_in[13];
    const float* Wdu  = (const float*)d_in[14];
    const float* bdu  = (const float*)d_in[15];
    const float* Wdl  = (const float*)d_in[16];
    const float* bdl  = (const float*)d_in[17];
    const float* Wdec = (const float*)d_in[18];
    const float* gdec = (const float*)d_in[19];
    const float* bdec = (const float*)d_in[20];
    const float* Wdep = (const float*)d_in[21];
    const float* gdep = (const float*)d_in[22];
    const float* bdep = (const float*)d_in[23];
    const float* Wg   = (const float*)d_in[24];
    const float* bg   = (const float*)d_in[25];
    const float* Wc   = (const float*)d_in[26];
    const float* bc   = (const float*)d_in[27];
    float* out = (float*)d_out;

    pool_k<<<(512 * HW + 255) / 256, 256>>>(xp, 0);
    pool_k<<<(120 * HW + 255) / 256, 256>>>(p_nodes, 1);
    keys_k<<<dim3(9, 12), 256>>>(Wk);
    q_k<<<dim3(9, 12), 256>>>(Wq);
    ugemm_k<<<dim3(35, 12), 256>>>(Wv, gv, bv, Wp);
    attn2_k<<<dim3(35, 12), 128>>>(gp, bp);
    upatt_k<<<dim3(36, 12), 256>>>(Watt, batt, out);
    dmap_k<<<(2 * PIX + 255) / 256, 256>>>(h_nodes, Wdu, bdu, Wdl, bdl, out);
    msg_k<<<dim3(36, 12), 256>>>(h_nodes, p_nodes,
                                 Wdec, gdec, bdec, Wdep, gdep, bdep,
                                 Wg, bg, Wc, bc, out);
}